// round 1
// baseline (speedup 1.0000x reference)
#include <cuda_runtime.h>
#include <math.h>

// Shapes (fixed for this problem)
#define BN   2048      // B*N nodes
#define NN   256       // neighbors per node (N)
#define DIN  128
#define DE   64
#define HH   128
#define MD   1664      // m_cat width = 128 + 12*128

// Scratch (device globals; no dynamic allocation allowed)
__device__ float g_hi[BN * DIN];
__device__ float g_hj[BN * DIN];
__device__ float g_m[(size_t)BN * MD];          // m_cat rows
__device__ float g_WihT[DIN * 3 * HH];          // 128 x 384
__device__ float g_WhhT[DIN * 3 * HH];          // 128 x 384

// ---------------------------------------------------------------------------
// K0: transpose GRU weight matrices (384x128 -> 128x384) for coalesced reads
// ---------------------------------------------------------------------------
__global__ void k0_transpose(const float* __restrict__ Wih,
                             const float* __restrict__ Whh) {
    int idx = blockIdx.x * 128 + threadIdx.x;   // grid 384 blocks
    if (idx < 384 * 128) {
        int r = idx >> 7;     // 0..383
        int c = idx & 127;    // 0..127
        g_WihT[c * 384 + r] = Wih[idx];
        g_WhhT[c * 384 + r] = Whh[idx];
    }
}

// ---------------------------------------------------------------------------
// K1: hi = input @ Wi, hj = input @ Wj; also copy input row into g_m[:,0:128]
// grid 128 blocks x 128 threads, 16 nodes per block
// ---------------------------------------------------------------------------
__global__ void __launch_bounds__(128) k1_hij(const float* __restrict__ input,
                                              const float* __restrict__ preW) {
    __shared__ float As[16 * 128];
    int t = threadIdx.x;
    int n0 = blockIdx.x * 16;

    for (int s = t; s < 16 * 128; s += 128) {
        float v = input[(size_t)n0 * 128 + s];
        As[s] = v;
        g_m[(size_t)(n0 + (s >> 7)) * MD + (s & 127)] = v;
    }
    __syncthreads();

    float hi[16], hj[16];
#pragma unroll
    for (int r = 0; r < 16; r++) { hi[r] = 0.f; hj[r] = 0.f; }

    for (int e = 0; e < 128; e += 4) {
        float wi0 = preW[(e + 0) * 128 + t];
        float wi1 = preW[(e + 1) * 128 + t];
        float wi2 = preW[(e + 2) * 128 + t];
        float wi3 = preW[(e + 3) * 128 + t];
        float wj0 = preW[(128 + e + 0) * 128 + t];
        float wj1 = preW[(128 + e + 1) * 128 + t];
        float wj2 = preW[(128 + e + 2) * 128 + t];
        float wj3 = preW[(128 + e + 3) * 128 + t];
#pragma unroll
        for (int r = 0; r < 16; r++) {
            const float4 a = *(const float4*)&As[r * 128 + e];
            hi[r] += a.x * wi0 + a.y * wi1 + a.z * wi2 + a.w * wi3;
            hj[r] += a.x * wj0 + a.y * wj1 + a.z * wj2 + a.w * wj3;
        }
    }
#pragma unroll
    for (int r = 0; r < 16; r++) {
        g_hi[(size_t)(n0 + r) * 128 + t] = hi[r];
        g_hj[(size_t)(n0 + r) * 128 + t] = hj[r];
    }
}

// ---------------------------------------------------------------------------
// K2: per-node sparse aggregation over neighbors.
// grid 2048 blocks (one node) x 128 threads (one output dim each).
// Neighbors processed in batches of 4 so each We smem read is reused 4x.
// ---------------------------------------------------------------------------
__global__ void __launch_bounds__(128) k2_agg(const float* __restrict__ adj,
                                              const float* __restrict__ adjf,
                                              const float* __restrict__ preW,
                                              const float* __restrict__ preb) {
    __shared__ float WeS[DE * 128];   // 32 KB: WeS[e*128 + k]
    __shared__ float efT[DE * 4];     // [e][u] transposed edge-feature batch
    __shared__ int   nbr[NN];
    __shared__ int   cnt;

    int t = threadIdx.x;
    int node = blockIdx.x;
    int nbase = (node >> 8) << 8;     // b*256

    // We rows are pre_W rows 256..319 (contiguous)
    for (int s = t; s < DE * 128; s += 128) WeS[s] = preW[256 * 128 + s];
    if (t == 0) cnt = 0;
    __syncthreads();

    const float* arow = adj + (size_t)node * NN;
    for (int j = t; j < NN; j += 128)
        if (arow[j] > 0.0f) { int p = atomicAdd(&cnt, 1); nbr[p] = j; }
    __syncthreads();

    int deg = cnt;
    float base = g_hi[(size_t)node * 128 + t] + preb[t];
    float s1 = 0.f, s2 = 0.f, mx = -1e30f, mn = 1e30f;
    const float* efb = adjf + (size_t)node * NN * DE;

    for (int p0 = 0; p0 < deg; p0 += 4) {
        int nb = deg - p0; if (nb > 4) nb = 4;
        __syncthreads();   // protect efT against previous-iteration readers
        for (int s = t; s < DE * 4; s += 128) {
            int u = s & 3, e = s >> 2;
            efT[s] = (u < nb) ? efb[(size_t)nbr[p0 + u] * DE + e] : 0.0f;
        }
        __syncthreads();

        // Prefetch hj for the batch (latency overlaps the 64-iter FMA loop)
        float hjv[4];
#pragma unroll
        for (int u = 0; u < 4; u++) {
            int uu = (u < nb) ? u : 0;
            int j = nbr[p0 + uu];
            hjv[u] = g_hj[(size_t)(nbase + j) * 128 + t];
        }

        float e0 = 0.f, e1 = 0.f, e2 = 0.f, e3 = 0.f;
#pragma unroll
        for (int e = 0; e < DE; e++) {
            float w = WeS[e * 128 + t];
            const float4 v = *(const float4*)&efT[e * 4];
            e0 += v.x * w; e1 += v.y * w; e2 += v.z * w; e3 += v.w * w;
        }
        float ev[4] = {e0, e1, e2, e3};
#pragma unroll
        for (int u = 0; u < 4; u++) {
            if (p0 + u < deg) {
                float tv = base + hjv[u] + ev[u];
                s1 += tv; s2 += tv * tv;
                mx = fmaxf(mx, tv); mn = fminf(mn, tv);
            }
        }
    }

    // Epilogue: build m_cat row (matches reference formulas exactly)
    float degf = (float)deg;
    float degc = fmaxf(degf, 1e-5f);
    float mean = s1 / degc;
    float var = s2 / degc - mean * mean;
    if (var < 0.f) var = 0.f;
    float sd = sqrtf(var + 1e-5f);
    float mxo = (deg > 0) ? mx : 0.f;
    float mno = (deg > 0) ? mn : 0.f;
    float slog = logf(degf + 1.0f) / 3.3f;
    float inv = 1.0f / (slog + 1e-5f);

    float* mrow = g_m + (size_t)node * MD;
    mrow[ 128 + t] = mean;        mrow[ 256 + t] = mxo;
    mrow[ 384 + t] = mno;         mrow[ 512 + t] = sd;
    mrow[ 640 + t] = mean * slog; mrow[ 768 + t] = mxo * slog;
    mrow[ 896 + t] = mno * slog;  mrow[1024 + t] = sd * slog;
    mrow[1152 + t] = mean * inv;  mrow[1280 + t] = mxo * inv;
    mrow[1408 + t] = mno * inv;   mrow[1536 + t] = sd * inv;
}

// ---------------------------------------------------------------------------
// K3: fused tail: y1 = m_cat @ post_W + b; y2 = leaky(y1 @ mix_W + b);
//     GRU cell -> out. grid 128 blocks x 256 threads; 16 nodes per block,
//     each thread owns (8 rows x 1 col).
// ---------------------------------------------------------------------------
__global__ void __launch_bounds__(256) k3_tail(const float* __restrict__ postW,
                                               const float* __restrict__ postb,
                                               const float* __restrict__ mixW,
                                               const float* __restrict__ mixb,
                                               const float* __restrict__ hidden,
                                               float* __restrict__ out) {
    __shared__ float As[16 * 64];
    __shared__ float Ys[16 * 128];
    __shared__ float Hs[16 * 128];

    int tid = threadIdx.x;
    int t = tid & 127;          // output column
    int half = tid >> 7;        // 0/1
    int rbase = half * 8;
    int n0 = blockIdx.x * 16;

    float acc[8];
#pragma unroll
    for (int r = 0; r < 8; r++) acc[r] = 0.f;

    // ---- y1 = m_cat @ post_W ----
    for (int kc = 0; kc < MD; kc += 64) {
        __syncthreads();
        for (int s = tid; s < 16 * 64; s += 256)
            As[s] = g_m[(size_t)(n0 + (s >> 6)) * MD + kc + (s & 63)];
        __syncthreads();
#pragma unroll
        for (int kk = 0; kk < 64; kk += 4) {
            const float* wp = postW + (size_t)(kc + kk) * 128 + t;
            float w0 = wp[0], w1 = wp[128], w2 = wp[256], w3 = wp[384];
#pragma unroll
            for (int r = 0; r < 8; r++) {
                const float4 a = *(const float4*)&As[(rbase + r) * 64 + kk];
                acc[r] += a.x * w0 + a.y * w1 + a.z * w2 + a.w * w3;
            }
        }
    }

    // hidden tile
    for (int s = tid; s < 16 * 128; s += 256)
        Hs[s] = hidden[(size_t)n0 * 128 + s];
    __syncthreads();

    float pb = postb[t];
#pragma unroll
    for (int r = 0; r < 8; r++) Ys[(rbase + r) * 128 + t] = acc[r] + pb;
    __syncthreads();

    // ---- y2 = leaky(y1 @ mix_W + mix_b) ----
#pragma unroll
    for (int r = 0; r < 8; r++) acc[r] = 0.f;
#pragma unroll
    for (int c = 0; c < 128; c += 4) {
        const float* wp = mixW + (size_t)c * 128 + t;
        float w0 = wp[0], w1 = wp[128], w2 = wp[256], w3 = wp[384];
#pragma unroll
        for (int r = 0; r < 8; r++) {
            const float4 a = *(const float4*)&Ys[(rbase + r) * 128 + c];
            acc[r] += a.x * w0 + a.y * w1 + a.z * w2 + a.w * w3;
        }
    }
    float mb = mixb[t];
    __syncthreads();
#pragma unroll
    for (int r = 0; r < 8; r++) {
        float y = acc[r] + mb;
        Ys[(rbase + r) * 128 + t] = (y > 0.f) ? y : 0.01f * y;
    }
    __syncthreads();

    // ---- GRU gates ----
    float Rg[8], Zg[8], Gin[8], Ghn[8];
#pragma unroll
    for (int r = 0; r < 8; r++) { Rg[r] = 0.f; Zg[r] = 0.f; Gin[r] = 0.f; Ghn[r] = 0.f; }

    for (int c = 0; c < 128; c += 4) {
        const float* wi = g_WihT + (size_t)c * 384 + t;
        const float* wh = g_WhhT + (size_t)c * 384 + t;
        float wir0 = wi[0],       wir1 = wi[384],       wir2 = wi[768],       wir3 = wi[1152];
        float wiz0 = wi[128],     wiz1 = wi[512],       wiz2 = wi[896],       wiz3 = wi[1280];
        float win0 = wi[256],     win1 = wi[640],       win2 = wi[1024],      win3 = wi[1408];
        float whr0 = wh[0],       whr1 = wh[384],       whr2 = wh[768],       whr3 = wh[1152];
        float whz0 = wh[128],     whz1 = wh[512],       whz2 = wh[896],       whz3 = wh[1280];
        float whn0 = wh[256],     whn1 = wh[640],       whn2 = wh[1024],      whn3 = wh[1408];
#pragma unroll
        for (int r = 0; r < 8; r++) {
            const float4 x = *(const float4*)&Ys[(rbase + r) * 128 + c];
            const float4 h = *(const float4*)&Hs[(rbase + r) * 128 + c];
            Rg[r]  += x.x * wir0 + x.y * wir1 + x.z * wir2 + x.w * wir3
                    + h.x * whr0 + h.y * whr1 + h.z * whr2 + h.w * whr3;
            Zg[r]  += x.x * wiz0 + x.y * wiz1 + x.z * wiz2 + x.w * wiz3
                    + h.x * whz0 + h.y * whz1 + h.z * whz2 + h.w * whz3;
            Gin[r] += x.x * win0 + x.y * win1 + x.z * win2 + x.w * win3;
            Ghn[r] += h.x * whn0 + h.y * whn1 + h.z * whn2 + h.w * whn3;
        }
    }

#pragma unroll
    for (int r = 0; r < 8; r++) {
        float R = 1.0f / (1.0f + expf(-Rg[r]));
        float Z = 1.0f / (1.0f + expf(-Zg[r]));
        float nn = tanhf(Gin[r] + R * Ghn[r]);
        float h = Hs[(rbase + r) * 128 + t];
        out[(size_t)(n0 + rbase + r) * 128 + t] = (1.0f - Z) * nn + Z * h;
    }
}

// ---------------------------------------------------------------------------
extern "C" void kernel_launch(void* const* d_in, const int* in_sizes, int n_in,
                              void* d_out, int out_size) {
    const float* input  = (const float*)d_in[0];
    const float* adj    = (const float*)d_in[1];
    const float* adjf   = (const float*)d_in[2];
    const float* hidden = (const float*)d_in[3];
    const float* preW   = (const float*)d_in[4];
    const float* preb   = (const float*)d_in[5];
    const float* postW  = (const float*)d_in[6];
    const float* postb  = (const float*)d_in[7];
    const float* mixW   = (const float*)d_in[8];
    const float* mixb   = (const float*)d_in[9];
    const float* Wih    = (const float*)d_in[10];
    const float* Whh    = (const float*)d_in[11];
    float* out = (float*)d_out;

    k0_transpose<<<384, 128>>>(Wih, Whh);
    k1_hij<<<128, 128>>>(input, preW);
    k2_agg<<<BN, 128>>>(adj, adjf, preW, preb);
    k3_tail<<<128, 256>>>(postW, postb, mixW, mixb, hidden, out);
}